// round 2
// baseline (speedup 1.0000x reference)
#include <cuda_runtime.h>
#include <cuda_bf16.h>
#include <math.h>

// Problem dims (fixed by setup_inputs)
#define MAXN 100000
#define MAXE 1600000
#define IN_DIM 128
#define HID 64   // hidden = out dim of layers

// Scratch (device globals: allocation-free rule)
__device__ float g_h[2][(size_t)MAXN * HID];   // ping-pong hidden states
__device__ float g_xn[(size_t)MAXN * HID];     // unit-normalized features
__device__ float g_s[MAXN];                    // norm + eps per node
__device__ int   g_rp[MAXN + 1];               // CSR row pointer (dest-sorted edges)

// ---------------------------------------------------------------------------
// row_ptr via binary search (edge_row is sorted ascending)
// ---------------------------------------------------------------------------
__global__ void rowptr_kernel(const int* __restrict__ row, int N, int E) {
    int t = blockIdx.x * blockDim.x + threadIdx.x;
    if (t > N) return;
    int lo = 0, hi = E;
    while (lo < hi) {
        int mid = (lo + hi) >> 1;
        if (row[mid] < t) lo = mid + 1; else hi = mid;
    }
    g_rp[t] = lo;
}

// ---------------------------------------------------------------------------
// Skinny GEMM: out[N,64] = x[N,K] @ W[64,K]^T + b  (optional ReLU)
// One warp computes 4 rows; each lane owns 2 output columns (2*lane, 2*lane+1).
// W transposed into smem as Wt[k][64]; x row fragments broadcast via shfl.
// ---------------------------------------------------------------------------
template <int K, bool RELU>
__global__ void gemm_kernel(const float* __restrict__ x_ext, int src_sel,
                            const float* __restrict__ W,
                            const float* __restrict__ b,
                            float* __restrict__ out_ext, int dst_sel, int N) {
    __shared__ float Wt[K * 64];
    for (int i = threadIdx.x; i < 64 * K; i += blockDim.x) {
        int o = i / K, k = i % K;
        Wt[k * 64 + o] = W[i];
    }
    __syncthreads();

    const float* xp  = x_ext  ? x_ext  : g_h[src_sel];
    float*       op  = out_ext ? out_ext : g_h[dst_sel];

    int warp = threadIdx.x >> 5, lane = threadIdx.x & 31;
    int row0 = (blockIdx.x * 8 + warp) * 4;
    if (row0 >= N) return;

    constexpr int J = K / 32;
    float xf[4][J];
#pragma unroll
    for (int r = 0; r < 4; r++) {
        int row = min(row0 + r, N - 1);
        const float* xr = xp + (size_t)row * K;
#pragma unroll
        for (int j = 0; j < J; j++) xf[r][j] = xr[j * 32 + lane];
    }

    float2 acc[4];
#pragma unroll
    for (int r = 0; r < 4; r++) acc[r] = make_float2(0.f, 0.f);

#pragma unroll
    for (int j = 0; j < J; j++) {
#pragma unroll
        for (int kk = 0; kk < 32; kk++) {
            float2 w = *(const float2*)&Wt[(j * 32 + kk) * 64 + 2 * lane];
#pragma unroll
            for (int r = 0; r < 4; r++) {
                float bx = __shfl_sync(0xffffffffu, xf[r][j], kk);
                acc[r].x = fmaf(bx, w.x, acc[r].x);
                acc[r].y = fmaf(bx, w.y, acc[r].y);
            }
        }
    }

    float2 bias = ((const float2*)b)[lane];
#pragma unroll
    for (int r = 0; r < 4; r++) {
        int row = row0 + r;
        if (row < N) {
            float fx = acc[r].x + bias.x;
            float fy = acc[r].y + bias.y;
            if (RELU) { fx = fmaxf(fx, 0.f); fy = fmaxf(fy, 0.f); }
            ((float2*)op)[(size_t)row * 32 + lane] = make_float2(fx, fy);
        }
    }
}

// ---------------------------------------------------------------------------
// Normalize: xn = h / (||h|| + eps), s = ||h|| + eps.  Warp per node.
// ---------------------------------------------------------------------------
__global__ void norm_kernel(int src_sel, int N) {
    int node = blockIdx.x * 8 + (threadIdx.x >> 5);
    if (node >= N) return;
    int lane = threadIdx.x & 31;
    const float2* h2 = (const float2*)g_h[src_sel];
    float2 v = h2[(size_t)node * 32 + lane];
    float p = v.x * v.x + v.y * v.y;
    p += __shfl_xor_sync(0xffffffffu, p, 16);
    p += __shfl_xor_sync(0xffffffffu, p, 8);
    p += __shfl_xor_sync(0xffffffffu, p, 4);
    p += __shfl_xor_sync(0xffffffffu, p, 2);
    p += __shfl_xor_sync(0xffffffffu, p, 1);
    float nrm = sqrtf(p) + 1e-12f;
    float inv = 1.0f / nrm;
    ((float2*)g_xn)[(size_t)node * 32 + lane] = make_float2(v.x * inv, v.y * inv);
    if (lane == 0) g_s[node] = nrm;
}

// ---------------------------------------------------------------------------
// AGNN propagation + ReLU. Warp per destination node, online softmax over the
// contiguous edge range [rp[i], rp[i+1]).  Accumulates sum(e * s[c] * xn[c]),
// divides by sum(e) at the end (== softmax attention over original h).
// ---------------------------------------------------------------------------
__global__ void prop_kernel(const int* __restrict__ colv, int dst_sel, int N) {
    int node = blockIdx.x * 8 + (threadIdx.x >> 5);
    if (node >= N) return;
    int lane = threadIdx.x & 31;

    const float2* xn2 = (const float2*)g_xn;
    int beg = g_rp[node], end = g_rp[node + 1];

    float2 xi = xn2[(size_t)node * 32 + lane];
    float m = -INFINITY, wsum = 0.f;
    float2 acc = make_float2(0.f, 0.f);

    for (int e = beg; e < end; ++e) {
        int c = __ldg(&colv[e]);
        float2 xc = xn2[(size_t)c * 32 + lane];
        float p = xi.x * xc.x + xi.y * xc.y;
        p += __shfl_xor_sync(0xffffffffu, p, 16);
        p += __shfl_xor_sync(0xffffffffu, p, 8);
        p += __shfl_xor_sync(0xffffffffu, p, 4);
        p += __shfl_xor_sync(0xffffffffu, p, 2);
        p += __shfl_xor_sync(0xffffffffu, p, 1);
        float sc = __ldg(&g_s[c]);
        float ev;
        if (p > m) {                       // warp-uniform branch (p reduced)
            float corr = __expf(m - p);    // first edge: exp(-inf)=0
            wsum *= corr; acc.x *= corr; acc.y *= corr;
            m = p; ev = 1.0f;
        } else {
            ev = __expf(p - m);
        }
        wsum += ev;
        float w = ev * sc;                 // fold back ||h_c||: h_c = s_c * xn_c
        acc.x = fmaf(w, xc.x, acc.x);
        acc.y = fmaf(w, xc.y, acc.y);
    }

    float inv = 1.0f / fmaxf(wsum, 1e-12f);
    float ox = fmaxf(acc.x * inv, 0.f);
    float oy = fmaxf(acc.y * inv, 0.f);
    ((float2*)g_h[dst_sel])[(size_t)node * 32 + lane] = make_float2(ox, oy);
}

// ---------------------------------------------------------------------------
extern "C" void kernel_launch(void* const* d_in, const int* in_sizes, int n_in,
                              void* d_out, int out_size) {
    const float* x    = (const float*)d_in[0];
    const int*   erow = (const int*)d_in[1];
    const int*   ecol = (const int*)d_in[2];
    const float* W1   = (const float*)d_in[3];
    const float* b1   = (const float*)d_in[4];
    const float* W2   = (const float*)d_in[5];
    const float* b2   = (const float*)d_in[6];

    int N = in_sizes[0] / IN_DIM;
    int E = in_sizes[1];

    // CSR row pointer from sorted edge_row
    rowptr_kernel<<<(N + 1 + 255) / 256, 256>>>(erow, N, E);

    int gemm_blocks = (N + 31) / 32;    // 8 warps * 4 rows per block
    int node_blocks = (N + 7) / 8;      // 8 warps (nodes) per block

    // h0 = relu(x @ W1^T + b1)
    gemm_kernel<IN_DIM, true><<<gemm_blocks, 256>>>(x, 0, W1, b1, nullptr, 0, N);

    int cur = 0;
    for (int l = 0; l < 4; l++) {
        norm_kernel<<<node_blocks, 256>>>(cur, N);
        prop_kernel<<<node_blocks, 256>>>(ecol, 1 - cur, N);
        cur = 1 - cur;
    }

    // out = h @ W2^T + b2
    gemm_kernel<HID, false><<<gemm_blocks, 256>>>(nullptr, cur, W2, b2,
                                                  (float*)d_out, 0, N);
}